// round 3
// baseline (speedup 1.0000x reference)
#include <cuda_runtime.h>

#define NN 10000
#define HID 16
#define LAB 7
#define KC 152
#define PITCH 153          // odd -> conflict-free scalar LDS
#define RPB 64
#define KSPLIT 2
#define NCHUNK 66          // ceil(10000/152), last chunk zero-padded
#define CH_PER 33

__device__ int g_is64;
__device__ __align__(16) float g_deg_src[NN];
__device__ __align__(16) float g_deg_dst[NN];
__device__ __align__(16) float g_norm_src[NN];
__device__ __align__(16) float g_norm_dst[NN];
__device__ __align__(16) float g_h[NN * HID];
__device__ __align__(16) float g_agg1[NN * HID];
__device__ __align__(16) float g_h2[NN * 8];
__device__ __align__(16) float g_agg2[NN * 8];

// ---------- helpers ----------
__device__ __forceinline__ unsigned long long pack2(float x) {
    unsigned long long r;
    asm("mov.b64 %0, {%1, %1};" : "=l"(r) : "f"(x));
    return r;
}
__device__ __forceinline__ void fma2(unsigned long long& d, unsigned long long a,
                                     unsigned long long b) {
    asm("fma.rn.f32x2 %0, %1, %2, %0;" : "+l"(d) : "l"(a), "l"(b));
}
__device__ __forceinline__ float2 unpack2(unsigned long long v) {
    float2 u;
    asm("mov.b64 {%0, %1}, %2;" : "=f"(u.x), "=f"(u.y) : "l"(v));
    return u;
}
__device__ __forceinline__ void redg_v4(float* p, float4 v) {
    unsigned long long gp;
    asm("cvta.to.global.u64 %0, %1;" : "=l"(gp) : "l"(p));
    asm volatile("red.global.add.v4.f32 [%0], {%1, %2, %3, %4};"
                 ::"l"(gp), "f"(v.x), "f"(v.y), "f"(v.z), "f"(v.w) : "memory");
}
__device__ __forceinline__ void redg_f32(float* p, float v) {
    unsigned long long gp;
    asm("cvta.to.global.u64 %0, %1;" : "=l"(gp) : "l"(p));
    asm volatile("red.global.add.f32 [%0], %1;" ::"l"(gp), "f"(v) : "memory");
}
// index read: int32, or low word of little-endian int64; clamp -> never traps
__device__ __forceinline__ int eidx(const void* p, int e, int is64) {
    int v = ((const int*)p)[is64 ? 2 * e : e];
    return min(max(v, 0), NN - 1);
}

// ---------- K0: detect dtype + zero scratch ----------
__global__ void k_init(const int* __restrict__ src) {
    int i = blockIdx.x * blockDim.x + threadIdx.x;
    if (i == 0) {
        int all_odd_zero = 1;
        for (int t = 1; t < 256; t += 2)
            if (src[t] != 0) { all_odd_zero = 0; break; }
        g_is64 = all_odd_zero;
    }
    int stride = gridDim.x * blockDim.x;
    for (int t = i; t < NN; t += stride) { g_deg_src[t] = 0.f; g_deg_dst[t] = 0.f; }
    for (int t = i; t < NN * HID; t += stride) { g_h[t] = 0.f; g_agg1[t] = 0.f; }
    for (int t = i; t < NN * 8; t += stride) g_agg2[t] = 0.f;
}

// ---------- K1: degrees ----------
__global__ void k_deg(const void* __restrict__ src, const void* __restrict__ dst, int nE) {
    int e = blockIdx.x * blockDim.x + threadIdx.x;
    if (e >= nE) return;
    int is64 = g_is64;
    redg_f32(&g_deg_src[eidx(src, e, is64)], 1.f);
    redg_f32(&g_deg_dst[eidx(dst, e, is64)], 1.f);
}

// ---------- K2: norms ----------
__global__ void k_norm() {
    int n = blockIdx.x * blockDim.x + threadIdx.x;
    if (n >= NN) return;
    g_norm_src[n] = rsqrtf(fmaxf(g_deg_src[n], 1.f));
    g_norm_dst[n] = rsqrtf(fmaxf(g_deg_dst[n], 1.f));
}

// ---------- K3: g_h = features @ W1 ----------
// 256 thr / 8 warps. Lane owns rows {lane, lane+32} of a 64-row block.
// Warps split K inside each staged chunk (19 j-steps each of KC=152).
// Per j: 4x LDS.128 (W row, uniform broadcast) + 2x LDS.32 (features,
// pitch 153 -> conflict-free) -> 16 FFMA2. grid.y = KSPLIT partial sums.
__global__ void __launch_bounds__(256)
k_gemm1(const float* __restrict__ feat, const float* __restrict__ W1) {
    __shared__ __align__(16) float sW[KC * HID];      // 9.5 KB
    __shared__ float sF[RPB * PITCH];                 // 38.3 KB

    const int rowBase = blockIdx.x * RPB;
    const int tid = threadIdx.x;
    const int w = tid >> 5;
    const int lane = tid & 31;

    unsigned long long a0[8], a1[8];
#pragma unroll
    for (int i = 0; i < 8; i++) { a0[i] = 0ull; a1[i] = 0ull; }

    const int ch0 = blockIdx.y * CH_PER;
    const int jBeg = w * (KC / 8);        // 19 j per warp

    for (int ch = ch0; ch < ch0 + CH_PER; ch++) {
        const int c0 = ch * KC;
        // stage features: coalesced scalar loads, conflict-free scalar STS
        for (int i = tid; i < RPB * KC; i += 256) {
            int r = i / KC, j = i - r * KC;
            int gr = rowBase + r, gc = c0 + j;
            float v = (gr < NN && gc < NN) ? feat[(size_t)gr * NN + gc] : 0.f;
            sF[r * PITCH + j] = v;
        }
        // stage W chunk (float4; zero-pad past NN rows)
        for (int i = tid; i < KC * HID / 4; i += 256) {
            int jr = i >> 2;
            float4 v = make_float4(0.f, 0.f, 0.f, 0.f);
            if (c0 + jr < NN) v = ((const float4*)(W1 + (size_t)(c0 + jr) * HID))[i & 3];
            ((float4*)sW)[i] = v;
        }
        __syncthreads();

        const float* fr0 = sF + lane * PITCH;
        const float* fr1 = sF + (lane + 32) * PITCH;
#pragma unroll
        for (int jj = 0; jj < KC / 8; jj++) {
            const int j = jBeg + jj;
            unsigned long long p0 = pack2(fr0[j]);
            unsigned long long p1 = pack2(fr1[j]);
            const ulonglong2* wr = (const ulonglong2*)(sW + j * HID);
            ulonglong2 q0 = wr[0], q1 = wr[1], q2 = wr[2], q3 = wr[3];
            fma2(a0[0], q0.x, p0); fma2(a0[1], q0.y, p0);
            fma2(a0[2], q1.x, p0); fma2(a0[3], q1.y, p0);
            fma2(a0[4], q2.x, p0); fma2(a0[5], q2.y, p0);
            fma2(a0[6], q3.x, p0); fma2(a0[7], q3.y, p0);
            fma2(a1[0], q0.x, p1); fma2(a1[1], q0.y, p1);
            fma2(a1[2], q1.x, p1); fma2(a1[3], q1.y, p1);
            fma2(a1[4], q2.x, p1); fma2(a1[5], q2.y, p1);
            fma2(a1[6], q3.x, p1); fma2(a1[7], q3.y, p1);
        }
        __syncthreads();
    }

    // cross-warp reduction: scratch 8 warps x 64 rows x 16 = 32 KB (reuse sF)
    float* red = sF;
#pragma unroll
    for (int i = 0; i < 8; i++) {
        float2 u0 = unpack2(a0[i]);
        float2 u1 = unpack2(a1[i]);
        red[(w * RPB + lane) * HID + 2 * i] = u0.x;
        red[(w * RPB + lane) * HID + 2 * i + 1] = u0.y;
        red[(w * RPB + lane + 32) * HID + 2 * i] = u1.x;
        red[(w * RPB + lane + 32) * HID + 2 * i + 1] = u1.y;
    }
    __syncthreads();
    for (int v = tid; v < RPB * HID; v += 256) {
        int r = v >> 4, k = v & 15;
        int gr = rowBase + r;
        if (gr < NN) {
            float s = 0.f;
#pragma unroll
            for (int ww = 0; ww < 8; ww++) s += red[(ww * RPB + r) * HID + k];
            redg_f32(&g_h[(size_t)gr * HID + k], s);
        }
    }
}

// ---------- K4: g_h *= norm_src (row-wise) ----------
__global__ void k_scale() {
    int i = blockIdx.x * blockDim.x + threadIdx.x;      // one float4 per thread
    if (i >= NN * HID / 4) return;
    float f = g_norm_src[i >> 2];
    float4 v = ((float4*)g_h)[i];
    v.x *= f; v.y *= f; v.z *= f; v.w *= f;
    ((float4*)g_h)[i] = v;
}

// ---------- K5: scatter layer 1 ----------
__global__ void k_scatter1(const void* __restrict__ src, const void* __restrict__ dst,
                           int nE) {
    int e = blockIdx.x * blockDim.x + threadIdx.x;
    if (e >= nE) return;
    int is64 = g_is64;
    int s = eidx(src, e, is64), d = eidx(dst, e, is64);
    const float4* hp = (const float4*)(g_h + (size_t)s * HID);
    float* ap = g_agg1 + (size_t)d * HID;
#pragma unroll
    for (int q = 0; q < 4; q++) redg_v4(ap + 4 * q, hp[q]);
}

// ---------- K6: h1 = relu(agg1*norm_dst + b1); h2 = (h1*norm_src) @ W2 ----------
__global__ void k_layer2(const float* __restrict__ b1, const float* __restrict__ W2) {
    int n = blockIdx.x * blockDim.x + threadIdx.x;
    if (n >= NN) return;
    float nd = g_norm_dst[n], ns = g_norm_src[n];
    float h1[HID];
    const float4* ap = (const float4*)(g_agg1 + (size_t)n * HID);
#pragma unroll
    for (int q = 0; q < 4; q++) {
        float4 v = ap[q];
        h1[4 * q + 0] = fmaxf(fmaf(v.x, nd, __ldg(&b1[4 * q + 0])), 0.f);
        h1[4 * q + 1] = fmaxf(fmaf(v.y, nd, __ldg(&b1[4 * q + 1])), 0.f);
        h1[4 * q + 2] = fmaxf(fmaf(v.z, nd, __ldg(&b1[4 * q + 2])), 0.f);
        h1[4 * q + 3] = fmaxf(fmaf(v.w, nd, __ldg(&b1[4 * q + 3])), 0.f);
    }
    float o[LAB];
#pragma unroll
    for (int j = 0; j < LAB; j++) o[j] = 0.f;
#pragma unroll
    for (int k = 0; k < HID; k++) {
        float hv = h1[k];
#pragma unroll
        for (int j = 0; j < LAB; j++) o[j] = fmaf(hv, __ldg(&W2[k * LAB + j]), o[j]);
    }
#pragma unroll
    for (int j = 0; j < LAB; j++) g_h2[n * 8 + j] = ns * o[j];
    g_h2[n * 8 + 7] = 0.f;
}

// ---------- K7: scatter layer 2 ----------
__global__ void k_scatter2(const void* __restrict__ src, const void* __restrict__ dst,
                           int nE) {
    int e = blockIdx.x * blockDim.x + threadIdx.x;
    if (e >= nE) return;
    int is64 = g_is64;
    int s = eidx(src, e, is64), d = eidx(dst, e, is64);
    const float4* hp = (const float4*)(g_h2 + (size_t)s * 8);
    float4 v0 = hp[0], v1 = hp[1];
    float* ap = g_agg2 + (size_t)d * 8;
    redg_v4(ap, v0);
    redg_v4(ap + 4, v1);
}

// ---------- K8: finalize ----------
__global__ void k_final(const float* __restrict__ b2, float* __restrict__ out) {
    int i = blockIdx.x * blockDim.x + threadIdx.x;
    if (i >= NN * LAB) return;
    int n = i / LAB, j = i - n * LAB;
    out[i] = fmaf(g_agg2[n * 8 + j], g_norm_dst[n], __ldg(&b2[j]));
}

extern "C" void kernel_launch(void* const* d_in, const int* in_sizes, int n_in,
                              void* d_out, int out_size) {
    const float* feat = (const float*)d_in[0];
    const void* src = d_in[1];
    const void* dst = d_in[2];
    const float* W1 = (const float*)d_in[3];
    const float* b1 = (const float*)d_in[4];
    const float* W2 = (const float*)d_in[5];
    const float* b2 = (const float*)d_in[6];
    int nE = in_sizes[1];
    float* out = (float*)d_out;

    int eb = (nE + 255) / 256;

    k_init<<<256, 256>>>((const int*)src);
    k_deg<<<eb, 256>>>(src, dst, nE);
    k_norm<<<(NN + 255) / 256, 256>>>();
    dim3 g1((NN + RPB - 1) / RPB, KSPLIT);     // 157 x 2
    k_gemm1<<<g1, 256>>>(feat, W1);
    k_scale<<<(NN * HID / 4 + 255) / 256, 256>>>();
    k_scatter1<<<eb, 256>>>(src, dst, nE);
    k_layer2<<<(NN + 255) / 256, 256>>>(b1, W2);
    k_scatter2<<<eb, 256>>>(src, dst, nE);
    k_final<<<(NN * LAB + 255) / 256, 256>>>(b2, out);
}

// round 4
// speedup vs baseline: 1.7099x; 1.7099x over previous
#include <cuda_runtime.h>

#define NN 10000
#define HID 16
#define LAB 7
#define KC 128            // k per chunk (floats)
#define KQ 32             // float4 per row chunk
#define RPB 64            // rows per block
#define PITCH4 33         // float4 pitch of staged feature rows (odd -> conflict-free)
#define NCH 79            // ceil(10000/128)

__device__ int g_is64;
__device__ __align__(16) float g_deg_src[NN];
__device__ __align__(16) float g_deg_dst[NN];
__device__ __align__(16) float g_norm_src[NN];
__device__ __align__(16) float g_norm_dst[NN];
__device__ __align__(16) float g_h[NN * HID];   // (features @ W1) * norm_src
__device__ __align__(16) float g_agg1[NN * HID];
__device__ __align__(16) float g_h2[NN * 8];
__device__ __align__(16) float g_agg2[NN * 8];

// ---------- helpers ----------
__device__ __forceinline__ unsigned long long pack2(float x) {
    unsigned long long r;
    asm("mov.b64 %0, {%1, %1};" : "=l"(r) : "f"(x));
    return r;
}
__device__ __forceinline__ void fma2(unsigned long long& d, unsigned long long a,
                                     unsigned long long b) {
    asm("fma.rn.f32x2 %0, %1, %2, %0;" : "+l"(d) : "l"(a), "l"(b));
}
__device__ __forceinline__ float2 unpack2(unsigned long long v) {
    float2 u;
    asm("mov.b64 {%0, %1}, %2;" : "=f"(u.x), "=f"(u.y) : "l"(v));
    return u;
}
__device__ __forceinline__ void redg_v4(float* p, float4 v) {
    unsigned long long gp;
    asm("cvta.to.global.u64 %0, %1;" : "=l"(gp) : "l"(p));
    asm volatile("red.global.add.v4.f32 [%0], {%1, %2, %3, %4};"
                 ::"l"(gp), "f"(v.x), "f"(v.y), "f"(v.z), "f"(v.w) : "memory");
}
__device__ __forceinline__ void redg_f32(float* p, float v) {
    unsigned long long gp;
    asm("cvta.to.global.u64 %0, %1;" : "=l"(gp) : "l"(p));
    asm volatile("red.global.add.f32 [%0], %1;" ::"l"(gp), "f"(v) : "memory");
}
// index read: int32, or low word of little-endian int64; clamp -> never traps
__device__ __forceinline__ int eidx(const void* p, int e, int is64) {
    int v = ((const int*)p)[is64 ? 2 * e : e];
    return min(max(v, 0), NN - 1);
}

// ---------- K0: detect dtype + zero scratch ----------
__global__ void k_init(const int* __restrict__ src) {
    int i = blockIdx.x * blockDim.x + threadIdx.x;
    if (i == 0) {
        int all_odd_zero = 1;
        for (int t = 1; t < 256; t += 2)
            if (src[t] != 0) { all_odd_zero = 0; break; }
        g_is64 = all_odd_zero;
    }
    int stride = gridDim.x * blockDim.x;
    for (int t = i; t < NN; t += stride) { g_deg_src[t] = 0.f; g_deg_dst[t] = 0.f; }
    for (int t = i; t < NN * HID; t += stride) g_agg1[t] = 0.f;
    for (int t = i; t < NN * 8; t += stride) g_agg2[t] = 0.f;
}

// ---------- K1: degrees ----------
__global__ void k_deg(const void* __restrict__ src, const void* __restrict__ dst, int nE) {
    int e = blockIdx.x * blockDim.x + threadIdx.x;
    if (e >= nE) return;
    int is64 = g_is64;
    redg_f32(&g_deg_src[eidx(src, e, is64)], 1.f);
    redg_f32(&g_deg_dst[eidx(dst, e, is64)], 1.f);
}

// ---------- K2: norms ----------
__global__ void k_norm() {
    int n = blockIdx.x * blockDim.x + threadIdx.x;
    if (n >= NN) return;
    g_norm_src[n] = rsqrtf(fmaxf(g_deg_src[n], 1.f));
    g_norm_dst[n] = rsqrtf(fmaxf(g_deg_dst[n], 1.f));
}

// ---------- K3: g_h = (features @ W1) * norm_src ----------
// 256 thr / 8 warps, 64 rows per block. Staging: warp w stages rows w+8i
// (lane = float4 quad -> 4x 128B coalesced lines per row), register
// double-buffered against compute. Compute: lane owns rows {lane, lane+32},
// warp w owns k in [w*16, w*16+16) of the chunk. Per 4 k: 2 LDS.128 feat
// (pitch 33 quads -> conflict-free) + 16 uniform LDS.128 W + 64 FFMA2.
// Epilogue: cross-warp smem reduce, scale by norm_src, direct STG.128.
__global__ void __launch_bounds__(256, 2)
k_gemm1(const float* __restrict__ feat, const float* __restrict__ W1) {
    __shared__ __align__(16) float sW[KC * HID];           // 8 KB
    __shared__ __align__(16) float sF[RPB * PITCH4 * 4];   // 33.8 KB

    const int tid = threadIdx.x;
    const int w = tid >> 5;
    const int lane = tid & 31;
    const int rowBase = blockIdx.x * RPB;

    unsigned long long a0[8], a1[8];
#pragma unroll
    for (int i = 0; i < 8; i++) { a0[i] = 0ull; a1[i] = 0ull; }

    const float4 z4 = make_float4(0.f, 0.f, 0.f, 0.f);
    float4 pre[8], wpre[2];
    const float4* W14 = (const float4*)W1;

    // prologue: load chunk 0
    {
        const int gc = lane * 4;
        const int okc = (gc < NN);
#pragma unroll
        for (int i = 0; i < 8; i++) {
            int gr = rowBase + w + 8 * i;
            pre[i] = (okc && gr < NN) ? *(const float4*)(feat + (size_t)gr * NN + gc) : z4;
        }
#pragma unroll
        for (int j = 0; j < 2; j++) {
            int q = tid + 256 * j;
            wpre[j] = (q < NN * 4) ? W14[q] : z4;
        }
    }

    float4* sF4 = (float4*)sF;
    float4* sW4 = (float4*)sW;

    for (int ch = 0; ch < NCH; ch++) {
        // store staged chunk
#pragma unroll
        for (int i = 0; i < 8; i++) sF4[(w + 8 * i) * PITCH4 + lane] = pre[i];
        sW4[tid] = wpre[0];
        sW4[tid + 256] = wpre[1];
        __syncthreads();

        // prefetch next chunk into registers (overlaps compute)
        if (ch + 1 < NCH) {
            const int c0n = (ch + 1) * KC;
            const int gc = c0n + lane * 4;
            const int okc = (gc < NN);
#pragma unroll
            for (int i = 0; i < 8; i++) {
                int gr = rowBase + w + 8 * i;
                pre[i] = (okc && gr < NN) ? *(const float4*)(feat + (size_t)gr * NN + gc) : z4;
            }
#pragma unroll
            for (int j = 0; j < 2; j++) {
                int q = c0n * 4 + tid + 256 * j;
                wpre[j] = (q < NN * 4) ? W14[q] : z4;
            }
        }

        // compute
#pragma unroll
        for (int kq4 = 0; kq4 < 4; kq4++) {
            const int kq = (w << 2) + kq4;
            float4 f0 = sF4[lane * PITCH4 + kq];
            float4 f1 = sF4[(lane + 32) * PITCH4 + kq];
            const float fa0[4] = {f0.x, f0.y, f0.z, f0.w};
            const float fa1[4] = {f1.x, f1.y, f1.z, f1.w};
#pragma unroll
            for (int m = 0; m < 4; m++) {
                const ulonglong2* wr = (const ulonglong2*)(sW + (kq * 4 + m) * HID);
                ulonglong2 q0 = wr[0], q1 = wr[1], q2 = wr[2], q3 = wr[3];
                unsigned long long p0 = pack2(fa0[m]);
                unsigned long long p1 = pack2(fa1[m]);
                fma2(a0[0], q0.x, p0); fma2(a0[1], q0.y, p0);
                fma2(a0[2], q1.x, p0); fma2(a0[3], q1.y, p0);
                fma2(a0[4], q2.x, p0); fma2(a0[5], q2.y, p0);
                fma2(a0[6], q3.x, p0); fma2(a0[7], q3.y, p0);
                fma2(a1[0], q0.x, p1); fma2(a1[1], q0.y, p1);
                fma2(a1[2], q1.x, p1); fma2(a1[3], q1.y, p1);
                fma2(a1[4], q2.x, p1); fma2(a1[5], q2.y, p1);
                fma2(a1[6], q3.x, p1); fma2(a1[7], q3.y, p1);
            }
        }
        __syncthreads();
    }

    // cross-warp reduce. Layout red[c][w][row]: writes conflict-free.
    float* red = sF;   // needs 16*8*64 = 8192 floats <= 8448
#pragma unroll
    for (int i = 0; i < 8; i++) {
        float2 u0 = unpack2(a0[i]);
        float2 u1 = unpack2(a1[i]);
        red[((2 * i) * 8 + w) * RPB + lane] = u0.x;
        red[((2 * i + 1) * 8 + w) * RPB + lane] = u0.y;
        red[((2 * i) * 8 + w) * RPB + lane + 32] = u1.x;
        red[((2 * i + 1) * 8 + w) * RPB + lane + 32] = u1.y;
    }
    __syncthreads();

    {
        const int r = tid >> 2;          // 0..63
        const int qc = tid & 3;          // float4 column group
        const int gr = rowBase + r;
        if (gr < NN) {
            float s[4] = {0.f, 0.f, 0.f, 0.f};
#pragma unroll
            for (int ww = 0; ww < 8; ww++) {
#pragma unroll
                for (int m = 0; m < 4; m++)
                    s[m] += red[((qc * 4 + m) * 8 + ww) * RPB + r];
            }
            float ns = g_norm_src[gr];
            float4 v = make_float4(s[0] * ns, s[1] * ns, s[2] * ns, s[3] * ns);
            ((float4*)g_h)[gr * 4 + qc] = v;
        }
    }
}

// ---------- K5: scatter layer 1 ----------
__global__ void k_scatter1(const void* __restrict__ src, const void* __restrict__ dst,
                           int nE) {
    int e = blockIdx.x * blockDim.x + threadIdx.x;
    if (e >= nE) return;
    int is64 = g_is64;
    int s = eidx(src, e, is64), d = eidx(dst, e, is64);
    const float4* hp = (const float4*)(g_h + (size_t)s * HID);
    float* ap = g_agg1 + (size_t)d * HID;
#pragma unroll
    for (int q = 0; q < 4; q++) redg_v4(ap + 4 * q, hp[q]);
}

// ---------- K6: h1 = relu(agg1*norm_dst + b1); h2 = (h1*norm_src) @ W2 ----------
__global__ void k_layer2(const float* __restrict__ b1, const float* __restrict__ W2) {
    int n = blockIdx.x * blockDim.x + threadIdx.x;
    if (n >= NN) return;
    float nd = g_norm_dst[n], ns = g_norm_src[n];
    float h1[HID];
    const float4* ap = (const float4*)(g_agg1 + (size_t)n * HID);
#pragma unroll
    for (int q = 0; q < 4; q++) {
        float4 v = ap[q];
        h1[4 * q + 0] = fmaxf(fmaf(v.x, nd, __ldg(&b1[4 * q + 0])), 0.f);
        h1[4 * q + 1] = fmaxf(fmaf(v.y, nd, __ldg(&b1[4 * q + 1])), 0.f);
        h1[4 * q + 2] = fmaxf(fmaf(v.z, nd, __ldg(&b1[4 * q + 2])), 0.f);
        h1[4 * q + 3] = fmaxf(fmaf(v.w, nd, __ldg(&b1[4 * q + 3])), 0.f);
    }
    float o[LAB];
#pragma unroll
    for (int j = 0; j < LAB; j++) o[j] = 0.f;
#pragma unroll
    for (int k = 0; k < HID; k++) {
        float hv = h1[k];
#pragma unroll
        for (int j = 0; j < LAB; j++) o[j] = fmaf(hv, __ldg(&W2[k * LAB + j]), o[j]);
    }
#pragma unroll
    for (int j = 0; j < LAB; j++) g_h2[n * 8 + j] = ns * o[j];
    g_h2[n * 8 + 7] = 0.f;
}

// ---------- K7: scatter layer 2 ----------
__global__ void k_scatter2(const void* __restrict__ src, const void* __restrict__ dst,
                           int nE) {
    int e = blockIdx.x * blockDim.x + threadIdx.x;
    if (e >= nE) return;
    int is64 = g_is64;
    int s = eidx(src, e, is64), d = eidx(dst, e, is64);
    const float4* hp = (const float4*)(g_h2 + (size_t)s * 8);
    float4 v0 = hp[0], v1 = hp[1];
    float* ap = g_agg2 + (size_t)d * 8;
    redg_v4(ap, v0);
    redg_v4(ap + 4, v1);
}

// ---------- K8: finalize ----------
__global__ void k_final(const float* __restrict__ b2, float* __restrict__ out) {
    int i = blockIdx.x * blockDim.x + threadIdx.x;
    if (i >= NN * LAB) return;
    int n = i / LAB, j = i - n * LAB;
    out[i] = fmaf(g_agg2[n * 8 + j], g_norm_dst[n], __ldg(&b2[j]));
}

extern "C" void kernel_launch(void* const* d_in, const int* in_sizes, int n_in,
                              void* d_out, int out_size) {
    const float* feat = (const float*)d_in[0];
    const void* src = d_in[1];
    const void* dst = d_in[2];
    const float* W1 = (const float*)d_in[3];
    const float* b1 = (const float*)d_in[4];
    const float* W2 = (const float*)d_in[5];
    const float* b2 = (const float*)d_in[6];
    int nE = in_sizes[1];
    float* out = (float*)d_out;

    int eb = (nE + 255) / 256;

    k_init<<<256, 256>>>((const int*)src);
    k_deg<<<eb, 256>>>(src, dst, nE);
    k_norm<<<(NN + 255) / 256, 256>>>();
    k_gemm1<<<(NN + RPB - 1) / RPB, 256>>>(feat, W1);   // 157 blocks
    k_scatter1<<<eb, 256>>>(src, dst, nE);
    k_layer2<<<(NN + 255) / 256, 256>>>(b1, W2);
    k_scatter2<<<eb, 256>>>(src, dst, nE);
    k_final<<<(NN * LAB + 255) / 256, 256>>>(b2, out);
}

// round 5
// speedup vs baseline: 2.3705x; 1.3863x over previous
#include <cuda_runtime.h>

#define NN 10000
#define HID 16
#define LAB 7
#define KC 64             // k per chunk
#define QC 16             // float4 per staged row chunk
#define RPB 64            // rows per block
#define PITCH4 17         // float4 pitch (odd -> conflict-free LDS.128)
#define NCH 157           // ceil(10000/64)
#define KSPLIT 4

__device__ int g_is64;
__device__ __align__(16) float g_deg_src[NN];
__device__ __align__(16) float g_deg_dst[NN];
__device__ __align__(16) float g_norm_src[NN];
__device__ __align__(16) float g_norm_dst[NN];
__device__ __align__(16) float g_h[NN * HID];
__device__ __align__(16) float g_agg1[NN * HID];
__device__ __align__(16) float g_h2[NN * 8];
__device__ __align__(16) float g_agg2[NN * 8];

// ---------- helpers ----------
__device__ __forceinline__ unsigned long long pack2(float x) {
    unsigned long long r;
    asm("mov.b64 %0, {%1, %1};" : "=l"(r) : "f"(x));
    return r;
}
__device__ __forceinline__ void fma2(unsigned long long& d, unsigned long long a,
                                     unsigned long long b) {
    asm("fma.rn.f32x2 %0, %1, %2, %0;" : "+l"(d) : "l"(a), "l"(b));
}
__device__ __forceinline__ float2 unpack2(unsigned long long v) {
    float2 u;
    asm("mov.b64 {%0, %1}, %2;" : "=f"(u.x), "=f"(u.y) : "l"(v));
    return u;
}
__device__ __forceinline__ void redg_v4(float* p, float4 v) {
    unsigned long long gp;
    asm("cvta.to.global.u64 %0, %1;" : "=l"(gp) : "l"(p));
    asm volatile("red.global.add.v4.f32 [%0], {%1, %2, %3, %4};"
                 ::"l"(gp), "f"(v.x), "f"(v.y), "f"(v.z), "f"(v.w) : "memory");
}
__device__ __forceinline__ void redg_f32(float* p, float v) {
    unsigned long long gp;
    asm("cvta.to.global.u64 %0, %1;" : "=l"(gp) : "l"(p));
    asm volatile("red.global.add.f32 [%0], %1;" ::"l"(gp), "f"(v) : "memory");
}
__device__ __forceinline__ void cp16(unsigned smem_dst, const void* gsrc, int sz) {
    asm volatile("cp.async.cg.shared.global [%0], [%1], 16, %2;"
                 ::"r"(smem_dst), "l"(gsrc), "r"(sz));
}
__device__ __forceinline__ int eidx(const void* p, int e, int is64) {
    int v = ((const int*)p)[is64 ? 2 * e : e];
    return min(max(v, 0), NN - 1);
}

// ---------- K0: detect dtype + zero scratch ----------
__global__ void k_init(const int* __restrict__ src) {
    int i = blockIdx.x * blockDim.x + threadIdx.x;
    if (i == 0) {
        int all_odd_zero = 1;
        for (int t = 1; t < 256; t += 2)
            if (src[t] != 0) { all_odd_zero = 0; break; }
        g_is64 = all_odd_zero;
    }
    int stride = gridDim.x * blockDim.x;
    for (int t = i; t < NN; t += stride) { g_deg_src[t] = 0.f; g_deg_dst[t] = 0.f; }
    for (int t = i; t < NN * HID; t += stride) { g_h[t] = 0.f; g_agg1[t] = 0.f; }
    for (int t = i; t < NN * 8; t += stride) g_agg2[t] = 0.f;
}

// ---------- K1: degrees ----------
__global__ void k_deg(const void* __restrict__ src, const void* __restrict__ dst, int nE) {
    int e = blockIdx.x * blockDim.x + threadIdx.x;
    if (e >= nE) return;
    int is64 = g_is64;
    redg_f32(&g_deg_src[eidx(src, e, is64)], 1.f);
    redg_f32(&g_deg_dst[eidx(dst, e, is64)], 1.f);
}

// ---------- K2: norms ----------
__global__ void k_norm() {
    int n = blockIdx.x * blockDim.x + threadIdx.x;
    if (n >= NN) return;
    g_norm_src[n] = rsqrtf(fmaxf(g_deg_src[n], 1.f));
    g_norm_dst[n] = rsqrtf(fmaxf(g_deg_dst[n], 1.f));
}

// ---------- K3: g_h += features @ W1 (partial over K-range) ----------
// cp.async double-buffered smem pipeline. 256 thr / 8 warps, 64 rows/block.
// Compute: lane owns rows {lane, lane+32}; warp w owns quads {2w, 2w+1} of the
// 16-quad chunk. Per k: 4 uniform LDS.128 (W row broadcast) + 16 FFMA2 x2rows.
__global__ void __launch_bounds__(256, 2)
k_gemm1(const float* __restrict__ feat, const float* __restrict__ W1) {
    __shared__ __align__(16) float4 sF[2][RPB * PITCH4];   // 2 x 17408 B
    __shared__ __align__(16) float4 sW[2][KC * HID / 4];   // 2 x 4096 B

    const int tid = threadIdx.x;
    const int w = tid >> 5;
    const int lane = tid & 31;
    const int rowBase = blockIdx.x * RPB;
    const int ks = blockIdx.y;
    const int ch0 = (ks * NCH) / KSPLIT;
    const int ch1 = ((ks + 1) * NCH) / KSPLIT;
    const int nch = ch1 - ch0;

    // per-thread staged copy coordinates (features): 4 quads
    const int fr = tid >> 4;          // row 0..15 base; +16 per iter
    const int fq = tid & 15;          // quad in row
    const float4* W14 = (const float4*)W1;

    // issue cp.async group for chunk (ch0+c) into buffer b
    auto issue = [&](int b, int c) {
        const int c0 = (ch0 + c) * KC;
#pragma unroll
        for (int i = 0; i < 4; i++) {
            int r = fr + 16 * i;
            int gr = rowBase + r;
            int gc = c0 + 4 * fq;
            int ok = (gr < NN && gc < NN);
            const float* src = feat + (size_t)min(gr, NN - 1) * NN + min(gc, NN - 4);
            cp16((unsigned)__cvta_generic_to_shared(&sF[b][r * PITCH4 + fq]), src,
                 ok ? 16 : 0);
        }
        {
            int gq = c0 * 4 + tid;    // global W quad
            int ok = (gq < NN * 4);
            cp16((unsigned)__cvta_generic_to_shared(&sW[b][tid]),
                 W14 + min(gq, NN * 4 - 1), ok ? 16 : 0);
        }
        asm volatile("cp.async.commit_group;" ::: "memory");
    };

    unsigned long long a0[8], a1[8];
#pragma unroll
    for (int i = 0; i < 8; i++) { a0[i] = 0ull; a1[i] = 0ull; }

    issue(0, 0);

    for (int c = 0; c < nch; c++) {
        const int b = c & 1;
        if (c + 1 < nch) {
            issue(b ^ 1, c + 1);
            asm volatile("cp.async.wait_group 1;" ::: "memory");
        } else {
            asm volatile("cp.async.wait_group 0;" ::: "memory");
        }
        __syncthreads();

        const float* wB = (const float*)sW[b];
#pragma unroll
        for (int t = 0; t < 2; t++) {
            const int kq = (w << 1) + t;
            float4 f0 = sF[b][lane * PITCH4 + kq];
            float4 f1 = sF[b][(lane + 32) * PITCH4 + kq];
            const float fa0[4] = {f0.x, f0.y, f0.z, f0.w};
            const float fa1[4] = {f1.x, f1.y, f1.z, f1.w};
#pragma unroll
            for (int m = 0; m < 4; m++) {
                const ulonglong2* wr = (const ulonglong2*)(wB + (kq * 4 + m) * HID);
                ulonglong2 q0 = wr[0], q1 = wr[1], q2 = wr[2], q3 = wr[3];
                unsigned long long p0 = pack2(fa0[m]);
                unsigned long long p1 = pack2(fa1[m]);
                fma2(a0[0], q0.x, p0); fma2(a0[1], q0.y, p0);
                fma2(a0[2], q1.x, p0); fma2(a0[3], q1.y, p0);
                fma2(a0[4], q2.x, p0); fma2(a0[5], q2.y, p0);
                fma2(a0[6], q3.x, p0); fma2(a0[7], q3.y, p0);
                fma2(a1[0], q0.x, p1); fma2(a1[1], q0.y, p1);
                fma2(a1[2], q1.x, p1); fma2(a1[3], q1.y, p1);
                fma2(a1[4], q2.x, p1); fma2(a1[5], q2.y, p1);
                fma2(a1[6], q3.x, p1); fma2(a1[7], q3.y, p1);
            }
        }
        __syncthreads();
    }

    // cross-warp reduce; reuse sF (needs 8192 floats <= 8704)
    float* red = (float*)sF;
#pragma unroll
    for (int i = 0; i < 8; i++) {
        float2 u0 = unpack2(a0[i]);
        float2 u1 = unpack2(a1[i]);
        red[((2 * i) * 8 + w) * RPB + lane] = u0.x;
        red[((2 * i + 1) * 8 + w) * RPB + lane] = u0.y;
        red[((2 * i) * 8 + w) * RPB + lane + 32] = u1.x;
        red[((2 * i + 1) * 8 + w) * RPB + lane + 32] = u1.y;
    }
    __syncthreads();
    {
        const int r = tid >> 2;
        const int qc = tid & 3;
        const int gr = rowBase + r;
        if (gr < NN) {
            float s[4] = {0.f, 0.f, 0.f, 0.f};
#pragma unroll
            for (int ww = 0; ww < 8; ww++)
#pragma unroll
                for (int m = 0; m < 4; m++)
                    s[m] += red[((qc * 4 + m) * 8 + ww) * RPB + r];
            redg_v4(&g_h[(size_t)gr * HID + qc * 4],
                    make_float4(s[0], s[1], s[2], s[3]));
        }
    }
}

// ---------- K4: g_h *= norm_src ----------
__global__ void k_scale() {
    int i = blockIdx.x * blockDim.x + threadIdx.x;
    if (i >= NN * HID / 4) return;
    float f = g_norm_src[i >> 2];
    float4 v = ((float4*)g_h)[i];
    v.x *= f; v.y *= f; v.z *= f; v.w *= f;
    ((float4*)g_h)[i] = v;
}

// ---------- K5: scatter layer 1 ----------
__global__ void k_scatter1(const void* __restrict__ src, const void* __restrict__ dst,
                           int nE) {
    int e = blockIdx.x * blockDim.x + threadIdx.x;
    if (e >= nE) return;
    int is64 = g_is64;
    int s = eidx(src, e, is64), d = eidx(dst, e, is64);
    const float4* hp = (const float4*)(g_h + (size_t)s * HID);
    float* ap = g_agg1 + (size_t)d * HID;
#pragma unroll
    for (int q = 0; q < 4; q++) redg_v4(ap + 4 * q, hp[q]);
}

// ---------- K6: h1 = relu(agg1*norm_dst + b1); h2 = (h1*norm_src) @ W2 ----------
__global__ void k_layer2(const float* __restrict__ b1, const float* __restrict__ W2) {
    int n = blockIdx.x * blockDim.x + threadIdx.x;
    if (n >= NN) return;
    float nd = g_norm_dst[n], ns = g_norm_src[n];
    float h1[HID];
    const float4* ap = (const float4*)(g_agg1 + (size_t)n * HID);
#pragma unroll
    for (int q = 0; q < 4; q++) {
        float4 v = ap[q];
        h1[4 * q + 0] = fmaxf(fmaf(v.x, nd, __ldg(&b1[4 * q + 0])), 0.f);
        h1[4 * q + 1] = fmaxf(fmaf(v.y, nd, __ldg(&b1[4 * q + 1])), 0.f);
        h1[4 * q + 2] = fmaxf(fmaf(v.z, nd, __ldg(&b1[4 * q + 2])), 0.f);
        h1[4 * q + 3] = fmaxf(fmaf(v.w, nd, __ldg(&b1[4 * q + 3])), 0.f);
    }
    float o[LAB];
#pragma unroll
    for (int j = 0; j < LAB; j++) o[j] = 0.f;
#pragma unroll
    for (int k = 0; k < HID; k++) {
        float hv = h1[k];
#pragma unroll
        for (int j = 0; j < LAB; j++) o[j] = fmaf(hv, __ldg(&W2[k * LAB + j]), o[j]);
    }
#pragma unroll
    for (int j = 0; j < LAB; j++) g_h2[n * 8 + j] = ns * o[j];
    g_h2[n * 8 + 7] = 0.f;
}

// ---------- K7: scatter layer 2 ----------
__global__ void k_scatter2(const void* __restrict__ src, const void* __restrict__ dst,
                           int nE) {
    int e = blockIdx.x * blockDim.x + threadIdx.x;
    if (e >= nE) return;
    int is64 = g_is64;
    int s = eidx(src, e, is64), d = eidx(dst, e, is64);
    const float4* hp = (const float4*)(g_h2 + (size_t)s * 8);
    float4 v0 = hp[0], v1 = hp[1];
    float* ap = g_agg2 + (size_t)d * 8;
    redg_v4(ap, v0);
    redg_v4(ap + 4, v1);
}

// ---------- K8: finalize ----------
__global__ void k_final(const float* __restrict__ b2, float* __restrict__ out) {
    int i = blockIdx.x * blockDim.x + threadIdx.x;
    if (i >= NN * LAB) return;
    int n = i / LAB, j = i - n * LAB;
    out[i] = fmaf(g_agg2[n * 8 + j], g_norm_dst[n], __ldg(&b2[j]));
}

extern "C" void kernel_launch(void* const* d_in, const int* in_sizes, int n_in,
                              void* d_out, int out_size) {
    const float* feat = (const float*)d_in[0];
    const void* src = d_in[1];
    const void* dst = d_in[2];
    const float* W1 = (const float*)d_in[3];
    const float* b1 = (const float*)d_in[4];
    const float* W2 = (const float*)d_in[5];
    const float* b2 = (const float*)d_in[6];
    int nE = in_sizes[1];
    float* out = (float*)d_out;

    int eb = (nE + 255) / 256;

    k_init<<<256, 256>>>((const int*)src);
    k_deg<<<eb, 256>>>(src, dst, nE);
    k_norm<<<(NN + 255) / 256, 256>>>();
    dim3 g1((NN + RPB - 1) / RPB, KSPLIT);     // 157 x 4 = 628 blocks
    k_gemm1<<<g1, 256>>>(feat, W1);
    k_scale<<<(NN * HID / 4 + 255) / 256, 256>>>();
    k_scatter1<<<eb, 256>>>(src, dst, nE);
    k_layer2<<<(NN + 255) / 256, 256>>>(b1, W2);
    k_scatter2<<<eb, 256>>>(src, dst, nE);
    k_final<<<(NN * LAB + 255) / 256, 256>>>(b2, out);
}